// round 14
// baseline (speedup 1.0000x reference)
#include <cuda_runtime.h>

// LIF-LSTM cell, fused fp32 GEMM + spike epilogue.
// Double-buffered (register-prefetch) version of the R3 kernel.
//
// gates[b, j] = sum_k hx[b,k]*Wh[j,k] + sum_k x[b,k]*Wi[j,k] + bh[j] + bi[j]
//   j in [0,4096): gate g = j/1024, n = j%1024
// i,f,c,o = spike(gate), spike(v) = (v >= 0.3)
// cy = f*cx + i*c ; hy = o * (cy >= 0.3)
// out = [hy (16384x1024) ; cy (16384x1024)]
//
// Shapes fixed: B=16384, ind=outd=1024, K=2048 (hx segment then x segment).
// Inputs (metadata order): x, hx, cx, Wh, bh, Wi, bi. All float32.

#define BM   128
#define BNN  32      // n per block (x4 gates = 128 effective N cols)
#define BK   16
#define NT   256
#define NK   128     // 2048 / BK

#define BATCH 16384
#define OUTD  1024
#define HALF_OUT (16384UL * 1024UL)

// Load tile t (BK k-slices) into registers. Gate-interleaved B mapping is
// applied at store time (store_tile), loads here are plain row-major.
__device__ __forceinline__ void load_tile(int t, int tid, int row0, int n0,
    const float* __restrict__ x,  const float* __restrict__ hx,
    const float* __restrict__ Wh, const float* __restrict__ Wi,
    float4 pa[2], float4 pb[2])
{
    const bool first = (t < 64);
    const float* __restrict__ Asrc = first ? hx : x;
    const float* __restrict__ Wsrc = first ? Wh : Wi;
    const int kloc = first ? (t * BK) : (t * BK - 1024);
#pragma unroll
    for (int l = 0; l < 2; l++) {
        const int idx = tid * 2 + l;
        const int r  = idx >> 2;          // 0..127
        const int kq = (idx & 3) * 4;     // 0,4,8,12
        pa[l] = *(const float4*)(Asrc + (size_t)(row0 + r) * 1024 + kloc + kq);
        const int g = r >> 5, nl = r & 31;
        pb[l] = *(const float4*)(Wsrc + (size_t)(g * 1024 + n0 + nl) * 1024 + kloc + kq);
    }
}

// Store registers into smem stage. As: [k][row]. Bs: [k][nl*4+g] (gate-interleaved
// so compute reads 8 consecutive floats per thread -> 2x LDS.128).
__device__ __forceinline__ void store_tile(float As[BK][BM], float Bs[BK][128],
                                           int tid, const float4 pa[2], const float4 pb[2])
{
#pragma unroll
    for (int l = 0; l < 2; l++) {
        const int idx = tid * 2 + l;
        const int r  = idx >> 2;
        const int kq = (idx & 3) * 4;
        As[kq + 0][r] = pa[l].x;
        As[kq + 1][r] = pa[l].y;
        As[kq + 2][r] = pa[l].z;
        As[kq + 3][r] = pa[l].w;
        const int g = r >> 5, nl = r & 31;
        const int cc = nl * 4 + g;
        Bs[kq + 0][cc] = pb[l].x;
        Bs[kq + 1][cc] = pb[l].y;
        Bs[kq + 2][cc] = pb[l].z;
        Bs[kq + 3][cc] = pb[l].w;
    }
}

__global__ __launch_bounds__(NT, 2)
void lif_lstm_fused_kernel(const float* __restrict__ x,
                           const float* __restrict__ hx,
                           const float* __restrict__ cx,
                           const float* __restrict__ Wh,
                           const float* __restrict__ bh,
                           const float* __restrict__ Wi,
                           const float* __restrict__ bi,
                           float* __restrict__ out)
{
    __shared__ float As[2][BK][BM];     // 16 KB
    __shared__ float Bs[2][BK][128];    // 16 KB

    const int row0 = blockIdx.x * BM;
    const int n0   = blockIdx.y * BNN;
    const int tid  = threadIdx.x;
    const int ty   = tid >> 4;          // 0..15 -> 8-row group
    const int tx   = tid & 15;          // 0..15 -> 2-n group (x4 gates)

    // acc[i][jn*4 + g] : row i, local n jn (0/1), gate g
    float acc[8][8];
#pragma unroll
    for (int i = 0; i < 8; i++)
#pragma unroll
        for (int j = 0; j < 8; j++) acc[i][j] = 0.0f;

    float4 pa[2], pb[2];
    load_tile(0, tid, row0, n0, x, hx, Wh, Wi, pa, pb);
    store_tile(As[0], Bs[0], tid, pa, pb);
    __syncthreads();

    for (int t = 0; t < NK; t++) {
        const int s = t & 1;
        // Prefetch next tile into registers (latency hidden by compute below).
        if (t + 1 < NK)
            load_tile(t + 1, tid, row0, n0, x, hx, Wh, Wi, pa, pb);

#pragma unroll
        for (int k = 0; k < BK; k++) {
            const float4 a0 = *(const float4*)&As[s][k][ty * 8];
            const float4 a1 = *(const float4*)&As[s][k][ty * 8 + 4];
            const float4 b0 = *(const float4*)&Bs[s][k][tx * 8];
            const float4 b1 = *(const float4*)&Bs[s][k][tx * 8 + 4];
            const float a[8] = {a0.x, a0.y, a0.z, a0.w, a1.x, a1.y, a1.z, a1.w};
            const float b[8] = {b0.x, b0.y, b0.z, b0.w, b1.x, b1.y, b1.z, b1.w};
#pragma unroll
            for (int i = 0; i < 8; i++)
#pragma unroll
                for (int j = 0; j < 8; j++)
                    acc[i][j] = fmaf(a[i], b[j], acc[i][j]);
        }

        // Write next stage. Safe without a pre-store sync: stage s^1 was last
        // READ at iteration t-1, and the sync at the end of t-1 ordered that.
        if (t + 1 < NK) {
            store_tile(As[s ^ 1], Bs[s ^ 1], tid, pa, pb);
            __syncthreads();
        }
    }

    // ---------------- epilogue ----------------
#pragma unroll
    for (int jn = 0; jn < 2; jn++) {
        const int n = n0 + tx * 2 + jn;
        const float bias_i = bh[0 * 1024 + n] + bi[0 * 1024 + n];
        const float bias_f = bh[1 * 1024 + n] + bi[1 * 1024 + n];
        const float bias_c = bh[2 * 1024 + n] + bi[2 * 1024 + n];
        const float bias_o = bh[3 * 1024 + n] + bi[3 * 1024 + n];
#pragma unroll
        for (int i = 0; i < 8; i++) {
            const int brow = row0 + ty * 8 + i;
            const float ig = acc[i][jn * 4 + 0] + bias_i;
            const float fg = acc[i][jn * 4 + 1] + bias_f;
            const float cg = acc[i][jn * 4 + 2] + bias_c;
            const float og = acc[i][jn * 4 + 3] + bias_o;
            const float ip = (ig >= 0.3f) ? 1.0f : 0.0f;
            const float fp = (fg >= 0.3f) ? 1.0f : 0.0f;
            const float cp = (cg >= 0.3f) ? 1.0f : 0.0f;
            const float op = (og >= 0.3f) ? 1.0f : 0.0f;
            const float cxv = cx[(size_t)brow * 1024 + n];
            const float cy  = fp * cxv + ip * cp;
            const float cyp = (cy >= 0.3f) ? 1.0f : 0.0f;
            const float hy  = op * cyp;
            out[(size_t)brow * 1024 + n]            = hy;
            out[HALF_OUT + (size_t)brow * 1024 + n] = cy;
        }
    }
}

extern "C" void kernel_launch(void* const* d_in, const int* in_sizes, int n_in,
                              void* d_out, int out_size)
{
    (void)in_sizes; (void)n_in; (void)out_size;
    const float* x  = (const float*)d_in[0];
    const float* hx = (const float*)d_in[1];
    const float* cx = (const float*)d_in[2];
    const float* Wh = (const float*)d_in[3];
    const float* bh = (const float*)d_in[4];
    const float* Wi = (const float*)d_in[5];
    const float* bi = (const float*)d_in[6];
    float* out = (float*)d_out;

    dim3 grid(BATCH / BM, OUTD / BNN);   // 128 x 32 = 4096 blocks
    lif_lstm_fused_kernel<<<grid, NT>>>(x, hx, cx, Wh, bh, Wi, bi, out);
}

// round 16
// speedup vs baseline: 1.6493x; 1.6493x over previous
#include <cuda_runtime.h>

// LIF-LSTM cell, fused fp32 GEMM + spike epilogue.
// Double-buffered (register-prefetch) GEMM; plain CUDA C only.
// R13 structure with __launch_bounds__(256,1): 255-reg budget removes the
// spills that sank R13 (regs=128 cap + L1=94% spill traffic).
//
// gates[b, j] = sum_k hx[b,k]*Wh[j,k] + sum_k x[b,k]*Wi[j,k] + bh[j] + bi[j]
//   j in [0,4096): gate g = j/1024, n = j%1024
// i,f,c,o = spike(gate), spike(v) = (v >= 0.3)
// cy = f*cx + i*c ; hy = o * (cy >= 0.3)
// out = [hy (16384x1024) ; cy (16384x1024)]
//
// Shapes fixed: B=16384, ind=outd=1024, K=2048 (hx segment then x segment).
// Inputs (metadata order): x, hx, cx, Wh, bh, Wi, bi. All float32.

#define BM   128
#define BNN  32      // n per block (x4 gates = 128 effective N cols)
#define BK   16
#define NT   256
#define NK   128     // 2048 / BK

#define BATCH 16384
#define OUTD  1024
#define HALF_OUT (16384UL * 1024UL)

// Load tile t (BK k-slices) into registers.
__device__ __forceinline__ void load_tile(int t, int tid, int row0, int n0,
    const float* __restrict__ x,  const float* __restrict__ hx,
    const float* __restrict__ Wh, const float* __restrict__ Wi,
    float4 pa[2], float4 pb[2])
{
    const bool first = (t < 64);
    const float* __restrict__ Asrc = first ? hx : x;
    const float* __restrict__ Wsrc = first ? Wh : Wi;
    const int kloc = first ? (t * BK) : (t * BK - 1024);
#pragma unroll
    for (int l = 0; l < 2; l++) {
        const int idx = tid * 2 + l;
        const int r  = idx >> 2;          // 0..127
        const int kq = (idx & 3) * 4;     // 0,4,8,12
        pa[l] = *(const float4*)(Asrc + (size_t)(row0 + r) * 1024 + kloc + kq);
        const int g = r >> 5, nl = r & 31;
        pb[l] = *(const float4*)(Wsrc + (size_t)(g * 1024 + n0 + nl) * 1024 + kloc + kq);
    }
}

// Store registers into smem stage. As: [k][row]. Bs: [k][nl*4+g]
// (gate-interleaved so each thread's 8 b-values are contiguous -> 2x LDS.128).
__device__ __forceinline__ void store_tile(float As[BK][BM], float Bs[BK][128],
                                           int tid, const float4 pa[2], const float4 pb[2])
{
#pragma unroll
    for (int l = 0; l < 2; l++) {
        const int idx = tid * 2 + l;
        const int r  = idx >> 2;
        const int kq = (idx & 3) * 4;
        As[kq + 0][r] = pa[l].x;
        As[kq + 1][r] = pa[l].y;
        As[kq + 2][r] = pa[l].z;
        As[kq + 3][r] = pa[l].w;
        const int g = r >> 5, nl = r & 31;
        const int cc = nl * 4 + g;
        Bs[kq + 0][cc] = pb[l].x;
        Bs[kq + 1][cc] = pb[l].y;
        Bs[kq + 2][cc] = pb[l].z;
        Bs[kq + 3][cc] = pb[l].w;
    }
}

__global__ __launch_bounds__(NT, 1)
void lif_lstm_fused_kernel(const float* __restrict__ x,
                           const float* __restrict__ hx,
                           const float* __restrict__ cx,
                           const float* __restrict__ Wh,
                           const float* __restrict__ bh,
                           const float* __restrict__ Wi,
                           const float* __restrict__ bi,
                           float* __restrict__ out)
{
    __shared__ float As[2][BK][BM];     // 16 KB
    __shared__ float Bs[2][BK][128];    // 16 KB

    const int row0 = blockIdx.x * BM;
    const int n0   = blockIdx.y * BNN;
    const int tid  = threadIdx.x;
    const int ty   = tid >> 4;          // 0..15 -> 8-row group
    const int tx   = tid & 15;          // 0..15 -> 2-n group (x4 gates)

    // acc[i][jn*4 + g] : row i, local n jn (0/1), gate g
    float acc[8][8];
#pragma unroll
    for (int i = 0; i < 8; i++)
#pragma unroll
        for (int j = 0; j < 8; j++) acc[i][j] = 0.0f;

    float4 pa[2], pb[2];
    load_tile(0, tid, row0, n0, x, hx, Wh, Wi, pa, pb);
    store_tile(As[0], Bs[0], tid, pa, pb);
    __syncthreads();

    for (int t = 0; t < NK; t++) {
        const int s = t & 1;
        // Prefetch next tile into registers (latency hidden by compute below).
        if (t + 1 < NK)
            load_tile(t + 1, tid, row0, n0, x, hx, Wh, Wi, pa, pb);

#pragma unroll
        for (int k = 0; k < BK; k++) {
            const float4 a0 = *(const float4*)&As[s][k][ty * 8];
            const float4 a1 = *(const float4*)&As[s][k][ty * 8 + 4];
            const float4 b0 = *(const float4*)&Bs[s][k][tx * 8];
            const float4 b1 = *(const float4*)&Bs[s][k][tx * 8 + 4];
            const float a[8] = {a0.x, a0.y, a0.z, a0.w, a1.x, a1.y, a1.z, a1.w};
            const float b[8] = {b0.x, b0.y, b0.z, b0.w, b1.x, b1.y, b1.z, b1.w};
#pragma unroll
            for (int i = 0; i < 8; i++)
#pragma unroll
                for (int j = 0; j < 8; j++)
                    acc[i][j] = fmaf(a[i], b[j], acc[i][j]);
        }

        // Write next stage. Stage s^1 was last READ in iteration t-1, and the
        // __syncthreads at the end of t-1 ordered those reads before this write.
        if (t + 1 < NK) {
            store_tile(As[s ^ 1], Bs[s ^ 1], tid, pa, pb);
            __syncthreads();
        }
    }

    // ---------------- epilogue ----------------
#pragma unroll
    for (int jn = 0; jn < 2; jn++) {
        const int n = n0 + tx * 2 + jn;
        const float bias_i = bh[0 * 1024 + n] + bi[0 * 1024 + n];
        const float bias_f = bh[1 * 1024 + n] + bi[1 * 1024 + n];
        const float bias_c = bh[2 * 1024 + n] + bi[2 * 1024 + n];
        const float bias_o = bh[3 * 1024 + n] + bi[3 * 1024 + n];
#pragma unroll
        for (int i = 0; i < 8; i++) {
            const int brow = row0 + ty * 8 + i;
            const float ig = acc[i][jn * 4 + 0] + bias_i;
            const float fg = acc[i][jn * 4 + 1] + bias_f;
            const float cg = acc[i][jn * 4 + 2] + bias_c;
            const float og = acc[i][jn * 4 + 3] + bias_o;
            const float ip = (ig >= 0.3f) ? 1.0f : 0.0f;
            const float fp = (fg >= 0.3f) ? 1.0f : 0.0f;
            const float cp = (cg >= 0.3f) ? 1.0f : 0.0f;
            const float op = (og >= 0.3f) ? 1.0f : 0.0f;
            const float cxv = cx[(size_t)brow * 1024 + n];
            const float cy  = fp * cxv + ip * cp;
            const float cyp = (cy >= 0.3f) ? 1.0f : 0.0f;
            const float hy  = op * cyp;
            out[(size_t)brow * 1024 + n]            = hy;
            out[HALF_OUT + (size_t)brow * 1024 + n] = cy;
        }
    }
}

extern "C" void kernel_launch(void* const* d_in, const int* in_sizes, int n_in,
                              void* d_out, int out_size)
{
    (void)in_sizes; (void)n_in; (void)out_size;
    const float* x  = (const float*)d_in[0];
    const float* hx = (const float*)d_in[1];
    const float* cx = (const float*)d_in[2];
    const float* Wh = (const float*)d_in[3];
    const float* bh = (const float*)d_in[4];
    const float* Wi = (const float*)d_in[5];
    const float* bi = (const float*)d_in[6];
    float* out = (float*)d_out;

    dim3 grid(BATCH / BM, OUTD / BNN);   // 128 x 32 = 4096 blocks
    lif_lstm_fused_kernel<<<grid, NT>>>(x, hx, cx, Wh, bh, Wi, bi, out);
}